// round 15
// baseline (speedup 1.0000x reference)
#include <cuda_runtime.h>
#include <cuda_bf16.h>
#include <math.h>
#include <stdint.h>

// Problem dims
#define B_    2
#define S_    2048
#define D_    1024
#define H_    16
#define DH_   64
#define NB_   32
#define NTOK  4096          // B_*S_
#define MLP_  4096
#define DE_   96            // extended head dim: 64 (content) + 32 (bucket)
#define DQKV  3072          // fused q|k|v row width

// ---------------- scratch (device globals; no allocations allowed) ----------------
__device__ __align__(128) float g_qkv [NTOK * DQKV];   // fused q|k|v (fp32)
__device__ __align__(128) float g_xres[NTOK * D_];
__device__ float g_mq  [H_ * NB_];
__device__ float g_mk  [H_ * NB_];

// bf16 activation buffers
__device__ __align__(128) __nv_bfloat16 g_xh [NTOK * D_];     // ln1 out (plain bf16)
__device__ __align__(128) __nv_bfloat16 g_aoh[NTOK * D_];     // attn out (plain bf16)
__device__ __align__(128) __nv_bfloat16 g_yh [NTOK * D_];     // ln2 out hi
__device__ __align__(128) __nv_bfloat16 g_yl [NTOK * D_];     // ln2 out lo
__device__ __align__(128) __nv_bfloat16 g_hh [NTOK * MLP_];   // mlp hidden hi
__device__ __align__(128) __nv_bfloat16 g_hl [NTOK * MLP_];   // mlp hidden lo
// transposed weights [N,K]: fused QKV + Wo plain bf16; W1/W2 hi/lo split
__device__ __align__(128) __nv_bfloat16 g_WqkvT[DQKV * D_];
__device__ __align__(128) __nv_bfloat16 g_WoT[D_ * D_];
__device__ __align__(128) __nv_bfloat16 g_W1Th[MLP_ * D_], g_W1Tl[MLP_ * D_];
__device__ __align__(128) __nv_bfloat16 g_W2Th[D_ * MLP_], g_W2Tl[D_ * MLP_];

// bf16 FA operands: extended q'/k' [(b*H+h)*S + s][96], V^T [(b*H+h)][dh][S]
__device__ __align__(128) __nv_bfloat16 g_qeb[NTOK * H_ * DE_];
__device__ __align__(128) __nv_bfloat16 g_keb[NTOK * H_ * DE_];
__device__ __align__(128) __nv_bfloat16 g_vt [B_ * H_ * DH_ * S_];

// ================= PTX helpers (baseline PTX only) =================================
__device__ __forceinline__ uint32_t smem_u32(const void* p) {
    uint32_t a;
    asm("{ .reg .u64 t; cvta.to.shared.u64 t, %1; cvt.u32.u64 %0, t; }" : "=r"(a) : "l"(p));
    return a;
}
__device__ __forceinline__ void cp16(uint32_t dst, const void* src) {
    asm volatile("cp.async.cg.shared.global [%0], [%1], 16;" :: "r"(dst), "l"(src));
}
__device__ __forceinline__ void cp_commit() {
    asm volatile("cp.async.commit_group;" ::: "memory");
}
__device__ __forceinline__ void ldm_x4(uint32_t* r, uint32_t a) {
    asm volatile("ldmatrix.sync.aligned.m8n8.x4.shared.b16 {%0,%1,%2,%3}, [%4];"
        : "=r"(r[0]), "=r"(r[1]), "=r"(r[2]), "=r"(r[3]) : "r"(a));
}
__device__ __forceinline__ void mma16816(float* d, const uint32_t* a, uint32_t b0, uint32_t b1) {
    asm volatile("mma.sync.aligned.m16n8k16.row.col.f32.bf16.bf16.f32 "
        "{%0,%1,%2,%3}, {%4,%5,%6,%7}, {%8,%9}, {%0,%1,%2,%3};"
        : "+f"(d[0]), "+f"(d[1]), "+f"(d[2]), "+f"(d[3])
        : "r"(a[0]), "r"(a[1]), "r"(a[2]), "r"(a[3]), "r"(b0), "r"(b1));
}
__device__ __forceinline__ void split_bf(float v, __nv_bfloat16& hi, __nv_bfloat16& lo) {
    hi = __float2bfloat16(v);
    lo = __float2bfloat16(v - __bfloat162float(hi));
}
__device__ __forceinline__ uint32_t packbf(float a, float b) {
    __nv_bfloat162 t = __floats2bfloat162_rn(a, b);
    return *(uint32_t*)&t;
}
__device__ __forceinline__ uint32_t swz(uint32_t off)   { return off ^ ((off >> 3) & 0x70u); }
// 64-byte-row swizzle (BK=32 tiles): XOR row[2:1] into the 16B-chunk index.
__device__ __forceinline__ uint32_t swz32(uint32_t off) { return off ^ ((off >> 3) & 0x30u); }

// ---------------- zero the loss accumulators ---------------------------------------
__global__ void zero_sums_k() {
    int i = threadIdx.x;
    if (i < H_ * NB_) { g_mq[i] = 0.f; g_mk[i] = 0.f; }
}

// ---------------- weight transpose + bf16 (optional hi/lo): W[K,N] -> WT[N,K] ------
__global__ void transpose_bf_k(const float* __restrict__ W,
                               __nv_bfloat16* __restrict__ WTh,
                               __nv_bfloat16* __restrict__ WTl, int K, int N) {
    __shared__ float t[32][33];
    int k0 = blockIdx.x * 32, n0 = blockIdx.y * 32;
    int tx = threadIdx.x, ty = threadIdx.y;   // 32 x 8
#pragma unroll
    for (int i = 0; i < 32; i += 8)
        t[ty + i][tx] = W[(size_t)(k0 + ty + i) * N + n0 + tx];
    __syncthreads();
#pragma unroll
    for (int i = 0; i < 32; i += 8) {
        float v = t[tx][ty + i];
        size_t o = (size_t)(n0 + ty + i) * K + k0 + tx;
        if (WTl) {
            __nv_bfloat16 hi, lo; split_bf(v, hi, lo);
            WTh[o] = hi; WTl[o] = lo;
        } else {
            WTh[o] = __float2bfloat16(v);
        }
    }
}

// ---------------- V transpose per head: g_qkv[token][2048+h*64+d] -> g_vt bf16 -----
__global__ void vt_k() {
    __shared__ float t[32][72];
    int bh = blockIdx.x;               // 0..31
    int s0 = blockIdx.y * 32;
    int b = bh >> 4, h = bh & 15;
    int tx = threadIdx.x, ty = threadIdx.y;  // 32 x 8
#pragma unroll
    for (int i = 0; i < 4; i++) {
        int s = ty + i * 8;
        const float* src = g_qkv + (size_t)(b * S_ + s0 + s) * DQKV + 2048 + h * DH_;
        t[s][tx]      = src[tx];
        t[s][tx + 32] = src[tx + 32];
    }
    __syncthreads();
#pragma unroll
    for (int i = 0; i < 8; i++) {
        int d = ty + i * 8;            // 0..63
        g_vt[((size_t)bh * DH_ + d) * S_ + s0 + tx] = __float2bfloat16(t[tx][d]);
    }
}

// ---------------- layernorm: bf16 out (optional lo) --------------------------------
__global__ void ln_k(const float* __restrict__ in, const float* __restrict__ g,
                     const float* __restrict__ b,
                     __nv_bfloat16* __restrict__ oh, __nv_bfloat16* __restrict__ ol) {
    int t = blockIdx.x, tid = threadIdx.x;
    const float* x = in + (size_t)t * D_;
    float v[4]; float s = 0.f, s2 = 0.f;
#pragma unroll
    for (int i = 0; i < 4; i++) { v[i] = x[tid + i * 256]; s += v[i]; s2 += v[i] * v[i]; }
#pragma unroll
    for (int o = 16; o; o >>= 1) {
        s  += __shfl_xor_sync(0xffffffffu, s,  o);
        s2 += __shfl_xor_sync(0xffffffffu, s2, o);
    }
    __shared__ float rs[8], rs2[8];
    __shared__ float mu_s, rstd_s;
    int w = tid >> 5, l = tid & 31;
    if (l == 0) { rs[w] = s; rs2[w] = s2; }
    __syncthreads();
    if (tid == 0) {
        float a = 0.f, a2 = 0.f;
        for (int i = 0; i < 8; i++) { a += rs[i]; a2 += rs2[i]; }
        float mu = a * (1.f / D_);
        float var = a2 * (1.f / D_) - mu * mu;
        mu_s = mu; rstd_s = rsqrtf(var + 1e-6f);
    }
    __syncthreads();
    float mu = mu_s, rstd = rstd_s;
#pragma unroll
    for (int i = 0; i < 4; i++) {
        int c = tid + i * 256;
        float vv = (v[i] - mu) * rstd * g[c] + b[c];
        if (ol) {
            __nv_bfloat16 hi, lo; split_bf(vv, hi, lo);
            oh[(size_t)t * D_ + c] = hi;
            ol[(size_t)t * D_ + c] = lo;
        } else {
            oh[(size_t)t * D_ + c] = __float2bfloat16(vv);
        }
    }
}

#define GBM 128
#define GBN 128
#define GBK 64

// ================= HMMA bf16 plain GEMM (fused QKV / Wo path), 2 CTAs/SM ===========
__global__ void __launch_bounds__(256, 2) hgemm_p_k(
    const __nv_bfloat16* __restrict__ Ah, const __nv_bfloat16* __restrict__ Bh,
    float* __restrict__ Cf, int M, int N, int K,
    const float* __restrict__ res)
{
    extern __shared__ char smem[];
    uint32_t sb = smem_u32(smem);
    uint32_t s0 = (sb + 1023u) & ~1023u;
    int tid = threadIdx.x, wid = tid >> 5, lane = tid & 31;
    int bn = blockIdx.x * GBN, bm = blockIdx.y * GBM;
    int wm = (wid & 3) * 32;
    int wn = (wid >> 2) * 64;

    auto prefetch = [&](int buf, int k0) {
        uint32_t base = s0 + (uint32_t)buf * 32768u;
#pragma unroll
        for (int i = 0; i < 4; i++) {
            int idx = tid + i * 256;
            int row = idx >> 3; int ch = (idx & 7) * 16;
            uint32_t sw = swz((uint32_t)(row * 128 + ch));
            cp16(base + sw,          (const char*)Ah + ((size_t)(bm + row) * K + k0) * 2 + ch);
            cp16(base + 16384u + sw, (const char*)Bh + ((size_t)(bn + row) * K + k0) * 2 + ch);
        }
        cp_commit();
    };

    prefetch(0, 0);
    prefetch(1, GBK);

    float acc[2][8][4];
#pragma unroll
    for (int i = 0; i < 2; i++)
#pragma unroll
        for (int j = 0; j < 8; j++)
#pragma unroll
            for (int c = 0; c < 4; c++) acc[i][j][c] = 0.f;

    int NK = K / GBK;
    for (int kt = 0; kt < NK; kt++) {
        int cur = kt & 1;
        if (kt == NK - 1) asm volatile("cp.async.wait_group 0;" ::: "memory");
        else              asm volatile("cp.async.wait_group 1;" ::: "memory");
        __syncthreads();

        uint32_t base = s0 + (uint32_t)cur * 32768u;
#pragma unroll
        for (int ks = 0; ks < 4; ks++) {
            int kb = ks * 32 + ((lane >> 4) << 4);
            uint32_t ah[2][4];
#pragma unroll
            for (int i = 0; i < 2; i++) {
                uint32_t sw = swz((uint32_t)((wm + i * 16 + (lane & 15)) * 128 + kb));
                ldm_x4(ah[i], base + sw);
            }
            uint32_t bh[4][4];
#pragma unroll
            for (int j = 0; j < 4; j++) {
                uint32_t sw = swz((uint32_t)((wn + j * 16 + (lane & 15)) * 128 + kb));
                ldm_x4(bh[j], base + 16384u + sw);
            }
#pragma unroll
            for (int i = 0; i < 2; i++)
#pragma unroll
                for (int j2 = 0; j2 < 8; j2++) {
                    int jj = j2 >> 1, e = j2 & 1;
                    mma16816(acc[i][j2], ah[i], bh[jj][e], bh[jj][2 + e]);
                }
        }
        __syncthreads();
        if (kt + 2 < NK) prefetch(cur, (kt + 2) * GBK);
    }

    float* stg = (float*)(smem + (s0 - sb));
#pragma unroll
    for (int i = 0; i < 2; i++)
#pragma unroll
        for (int j2 = 0; j2 < 8; j2++) {
            int r0 = wm + i * 16 + (lane >> 2);
            int c0 = wn + j2 * 8 + 2 * (lane & 3);
            stg[r0 * 132 + c0]           = acc[i][j2][0];
            stg[r0 * 132 + c0 + 1]       = acc[i][j2][1];
            stg[(r0 + 8) * 132 + c0]     = acc[i][j2][2];
            stg[(r0 + 8) * 132 + c0 + 1] = acc[i][j2][3];
        }
    __syncthreads();
#pragma unroll
    for (int i = 0; i < 64; i++) {
        int idx = tid + i * 256;
        int rr = idx >> 7, cc = idx & 127;
        int gr = bm + rr, gc = bn + cc;
        float v = stg[rr * 132 + cc];
        if (res) v += res[(size_t)gr * N + gc];
        Cf[(size_t)gr * N + gc] = v;
    }
}

// ================= HMMA bf16 split-3 GEMM: 128x128 tile, BK=32, 2 CTAs/SM ==========
// C = Ah·Bh + Al·Bh + Ah·Bl (fp32 accum, ~fp32 accuracy).
// Stage (32KB): Ah@0(8K), Al@8K, Bh@16K, Bl@24K; 64B rows, swz32 swizzle.
__global__ void __launch_bounds__(256, 2) hgemm2_k(
    const __nv_bfloat16* __restrict__ Ah, const __nv_bfloat16* __restrict__ Al,
    const __nv_bfloat16* __restrict__ Bh, const __nv_bfloat16* __restrict__ Bl,
    float* __restrict__ Cf,
    __nv_bfloat16* __restrict__ Cbh, __nv_bfloat16* __restrict__ Cbl,
    int M, int N, int K,
    const float* __restrict__ bias, const float* __restrict__ res, int relu)
{
    extern __shared__ char smem[];
    uint32_t sb = smem_u32(smem);
    uint32_t s0 = (sb + 1023u) & ~1023u;
    int tid = threadIdx.x, wid = tid >> 5, lane = tid & 31;
    int bn = blockIdx.x * GBN, bm = blockIdx.y * GBM;
    int wm = (wid & 3) * 32;                 // 4 warps over M=128
    int wn = (wid >> 2) * 64;                // 2 warps over N=128

    auto prefetch = [&](int buf, int k0) {
        uint32_t base = s0 + (uint32_t)buf * 32768u;
        // A hi/lo: 128 rows x 4 chunks(16B); B hi/lo: same
#pragma unroll
        for (int i = 0; i < 2; i++) {
            int idx = tid + i * 256;
            int row = idx >> 2; int ch = (idx & 3) * 16;
            uint32_t sw = swz32((uint32_t)(row * 64 + ch));
            size_t ga = ((size_t)(bm + row) * K + k0) * 2 + ch;
            size_t gb = ((size_t)(bn + row) * K + k0) * 2 + ch;
            cp16(base + sw,           (const char*)Ah + ga);
            cp16(base + 8192u + sw,   (const char*)Al + ga);
            cp16(base + 16384u + sw,  (const char*)Bh + gb);
            cp16(base + 24576u + sw,  (const char*)Bl + gb);
        }
        cp_commit();
    };

    prefetch(0, 0);
    prefetch(1, 32);

    float acc[2][8][4];
#pragma unroll
    for (int i = 0; i < 2; i++)
#pragma unroll
        for (int j = 0; j < 8; j++)
#pragma unroll
            for (int c = 0; c < 4; c++) acc[i][j][c] = 0.f;

    int NK = K / 32;
    for (int kt = 0; kt < NK; kt++) {
        int cur = kt & 1;
        if (kt == NK - 1) asm volatile("cp.async.wait_group 0;" ::: "memory");
        else              asm volatile("cp.async.wait_group 1;" ::: "memory");
        __syncthreads();

        uint32_t base = s0 + (uint32_t)cur * 32768u;
#pragma unroll
        for (int ks = 0; ks < 2; ks++) {
            int kb = ks * 32 + ((lane >> 4) << 4);   // byte col within 64B row
            uint32_t ah[2][4], al2[2][4];
#pragma unroll
            for (int i = 0; i < 2; i++) {
                uint32_t sw = swz32((uint32_t)((wm + i * 16 + (lane & 15)) * 64 + kb));
                ldm_x4(ah[i],  base + sw);
                ldm_x4(al2[i], base + 8192u + sw);
            }
            uint32_t bh2[4][4], bl2[4][4];
#pragma unroll
            for (int j = 0; j < 4; j++) {
                uint32_t sw = swz32((uint32_t)((wn + j * 16 + (lane & 15)) * 64 + kb));
                ldm_x4(bh2[j], base + 16384u + sw);
                ldm_x4(bl2[j], base + 24576u + sw);
            }
#pragma unroll
            for (int i = 0; i < 2; i++)
#pragma unroll
                for (int j2 = 0; j2 < 8; j2++) {
                    int jj = j2 >> 1, e = j2 & 1;
                    uint32_t b0 = bh2[jj][e], b1 = bh2[jj][2 + e];
                    uint32_t c0 = bl2[jj][e], c1 = bl2[jj][2 + e];
                    mma16816(acc[i][j2], ah[i],  b0, b1);
                    mma16816(acc[i][j2], al2[i], b0, b1);
                    mma16816(acc[i][j2], ah[i],  c0, c1);
                }
        }
        __syncthreads();
        if (kt + 2 < NK) prefetch(cur, (kt + 2) * 32);
    }

    // epilogue: stage fp32 through smem (aliases tile buffers)
    float* stg = (float*)(smem + (s0 - sb));
#pragma unroll
    for (int i = 0; i < 2; i++)
#pragma unroll
        for (int j2 = 0; j2 < 8; j2++) {
            int r0 = wm + i * 16 + (lane >> 2);
            int c0 = wn + j2 * 8 + 2 * (lane & 3);
            stg[r0 * 132 + c0]           = acc[i][j2][0];
            stg[r0 * 132 + c0 + 1]       = acc[i][j2][1];
            stg[(r0 + 8) * 132 + c0]     = acc[i][j2][2];
            stg[(r0 + 8) * 132 + c0 + 1] = acc[i][j2][3];
        }
    __syncthreads();

    if (Cbh) {
#pragma unroll
        for (int i = 0; i < 32; i++) {       // 128 x 64 bf162 pairs
            int idx = tid + i * 256;
            int rr = idx >> 6, cp = idx & 63;
            int gr = bm + rr, gc = bn + 2 * cp;
            float v0 = stg[rr * 132 + 2 * cp];
            float v1 = stg[rr * 132 + 2 * cp + 1];
            if (bias) { v0 += bias[gc]; v1 += bias[gc + 1]; }
            if (res)  { v0 += res[(size_t)gr * N + gc]; v1 += res[(size_t)gr * N + gc + 1]; }
            if (relu) { v0 = fmaxf(v0, 0.f); v1 = fmaxf(v1, 0.f); }
            __nv_bfloat16 h0, l0, h1, l1;
            split_bf(v0, h0, l0); split_bf(v1, h1, l1);
            __nv_bfloat162 hh2; hh2.x = h0; hh2.y = h1;
            __nv_bfloat162 ll2; ll2.x = l0; ll2.y = l1;
            *(__nv_bfloat162*)&Cbh[(size_t)gr * N + gc] = hh2;
            *(__nv_bfloat162*)&Cbl[(size_t)gr * N + gc] = ll2;
        }
    } else {
#pragma unroll
        for (int i = 0; i < 64; i++) {       // 128 x 128 floats
            int idx = tid + i * 256;
            int rr = idx >> 7, cc = idx & 127;
            int gr = bm + rr, gc = bn + cc;
            float v = stg[rr * 132 + cc];
            if (bias) v += bias[gc];
            if (res)  v += res[(size_t)gr * N + gc];
            if (relu) v = fmaxf(v, 0.f);
            Cf[(size_t)gr * N + gc] = v;
        }
    }
}

// ---------------- bucket softmax + extended q'/k' build (bf16) + loss --------------
__global__ void build_ext_k(const float* __restrict__ Whq, const float* __restrict__ Whk) {
    int wg   = blockIdx.x * 4 + (threadIdx.x >> 5);
    int lane = threadIdx.x & 31;
    int t = wg >> 4, h = wg & 15;
    int b = t >> 11, s = t & 2047;
    const float* q = g_qkv + (size_t)t * DQKV + h * DH_;
    const float* k = g_qkv + (size_t)t * DQKV + 1024 + h * DH_;
    float ql = 0.f, kl = 0.f;
#pragma unroll 8
    for (int f = 0; f < DH_; f++) {
        float qv = q[f], kv = k[f];
        ql += qv * Whq[(h * DH_ + f) * NB_ + lane];
        kl += kv * Whk[(h * DH_ + f) * NB_ + lane];
    }
    float mq = ql, mk = kl;
#pragma unroll
    for (int o = 16; o; o >>= 1) {
        mq = fmaxf(mq, __shfl_xor_sync(0xffffffffu, mq, o));
        mk = fmaxf(mk, __shfl_xor_sync(0xffffffffu, mk, o));
    }
    float eq = __expf(ql - mq), ek = __expf(kl - mk);
    float sq = eq, sk = ek;
#pragma unroll
    for (int o = 16; o; o >>= 1) {
        sq += __shfl_xor_sync(0xffffffffu, sq, o);
        sk += __shfl_xor_sync(0xffffffffu, sk, o);
    }
    float qb = eq / sq, kb = ek / sk;
    size_t base = ((size_t)(b * H_ + h) * S_ + s) * DE_;
    __nv_bfloat16* qe = g_qeb + base;
    __nv_bfloat16* ke = g_keb + base;
    qe[64 + lane] = __float2bfloat16(0.1f * qb);   // cluster weight folded into q'
    ke[64 + lane] = __float2bfloat16(kb);
    qe[lane]      = __float2bfloat16(0.125f * q[lane]);
    qe[lane + 32] = __float2bfloat16(0.125f * q[lane + 32]);
    ke[lane]      = __float2bfloat16(k[lane]);
    ke[lane + 32] = __float2bfloat16(k[lane + 32]);
    atomicAdd(&g_mq[h * NB_ + lane], qb);
    atomicAdd(&g_mk[h * NB_ + lane], kb);
}

// ================= HMMA flash attention ============================================
#define FQM 128
__global__ void __launch_bounds__(256) fa_k() {
    extern __shared__ char smem[];
    uint32_t sb = smem_u32(smem);
    uint32_t s0 = (sb + 1023u) & ~1023u;
    uint32_t Q0 = s0, Q1 = s0 + 16384u;            // Q content / bucket subtiles
    uint32_t KV = s0 + 32768u;                     // 2 x 24KB: K0,K1,Vt per buffer
    int tid = threadIdx.x, wid = tid >> 5, lane = tid & 31;
    int blk = blockIdx.x;
    int qt = blk & 15, h = (blk >> 4) & 15, b = blk >> 8;
    int bh = b * H_ + h;
    int t0q = b * S_ + qt * FQM;

    const char* qsrc = (const char*)(g_qeb + ((size_t)bh * S_ + qt * FQM) * DE_);
    const char* ksrc0 = (const char*)(g_keb + (size_t)bh * S_ * DE_);
    const char* vsrc0 = (const char*)(g_vt + (size_t)bh * DH_ * S_);

#pragma unroll
    for (int i = 0; i < 6; i++) {
        int idx = tid + i * 256;
        int row = idx / 12, c = idx - row * 12;
        uint32_t dst = (c < 8) ? (Q0 + swz((uint32_t)(row * 128 + c * 16)))
                               : (Q1 + swz((uint32_t)(row * 128 + (c - 8) * 16)));
        cp16(dst, qsrc + (size_t)row * (DE_ * 2) + c * 16);
    }
    cp_commit();

    auto prefetch = [&](int buf, int kt) {
        uint32_t base = KV + (uint32_t)buf * 24576u;
        const char* ks = ksrc0 + (size_t)(kt * 64) * (DE_ * 2);
#pragma unroll
        for (int i = 0; i < 3; i++) {
            int idx = tid + i * 256;
            int row = idx / 12, c = idx - row * 12;
            uint32_t dst = (c < 8) ? (base + swz((uint32_t)(row * 128 + c * 16)))
                                   : (base + 8192u + swz((uint32_t)(row * 128 + (c - 8) * 16)));
            cp16(dst, ks + (size_t)row * (DE_ * 2) + c * 16);
        }
#pragma unroll
        for (int i = 0; i < 2; i++) {
            int idx = tid + i * 256;
            int row = idx >> 3, c = idx & 7;
            cp16(base + 16384u + swz((uint32_t)(row * 128 + c * 16)),
                 vsrc0 + (size_t)row * (S_ * 2) + kt * 128 + c * 16);
        }
        cp_commit();
    };

    prefetch(0, 0);
    asm volatile("cp.async.wait_group 1;" ::: "memory");
    __syncthreads();

    uint32_t qf[6][4];
#pragma unroll
    for (int ks = 0; ks < 6; ks++) {
        uint32_t base = (ks < 4) ? Q0 : Q1;
        int kb = ((ks < 4) ? ks * 32 : (ks - 4) * 32) + ((lane >> 4) << 4);
        ldm_x4(qf[ks], base + swz((uint32_t)((wid * 16 + (lane & 15)) * 128 + kb)));
    }

    float o[8][4];
#pragma unroll
    for (int j = 0; j < 8; j++)
#pragma unroll
        for (int c = 0; c < 4; c++) o[j][c] = 0.f;
    float mrow[2] = {-1e30f, -1e30f}, lrow[2] = {0.f, 0.f};

    const int NT = S_ / 64;
    for (int kt = 0; kt < NT; kt++) {
        int cur = kt & 1;
        if (kt + 1 < NT) { prefetch(cur ^ 1, kt + 1); asm volatile("cp.async.wait_group 1;" ::: "memory"); }
        else             { asm volatile("cp.async.wait_group 0;" ::: "memory"); }
        __syncthreads();

        uint32_t kbase = KV + (uint32_t)cur * 24576u;

        float s[8][4];
#pragma unroll
        for (int j = 0; j < 8; j++)
#pragma unroll
            for (int c = 0; c < 4; c++) s[j][c] = 0.f;
#pragma unroll
        for (int ks = 0; ks < 6; ks++) {
            uint32_t base = (ks < 4) ? kbase : (kbase + 8192u);
            int kb = ((ks < 4) ? ks * 32 : (ks - 4) * 32) + ((lane >> 4) << 4);
            uint32_t bf[4][4];
#pragma unroll
            for (int j = 0; j < 4; j++)
                ldm_x4(bf[j], base + swz((uint32_t)((j * 16 + (lane & 15)) * 128 + kb)));
#pragma unroll
            for (int j2 = 0; j2 < 8; j2++) {
                int jj = j2 >> 1, e = j2 & 1;
                mma16816(s[j2], qf[ks], bf[jj][e], bf[jj][2 + e]);
            }
        }

        float fac[2];
#pragma unroll
        for (int hf = 0; hf < 2; hf++) {
            float mt = -1e30f;
#pragma unroll
            for (int j = 0; j < 8; j++)
                mt = fmaxf(mt, fmaxf(s[j][2 * hf], s[j][2 * hf + 1]));
            mt = fmaxf(mt, __shfl_xor_sync(0xffffffffu, mt, 1));
            mt = fmaxf(mt, __shfl_xor_sync(0xffffffffu, mt, 2));
            float mn = fmaxf(mrow[hf], mt);
            fac[hf] = __expf(mrow[hf] - mn);
            float ps = 0.f;
#pragma unroll
            for (int j = 0; j < 8; j++) {
                float p0 = __expf(s[j][2 * hf]     - mn);
                float p1 = __expf(s[j][2 * hf + 1] - mn);
                s[j][2 * hf] = p0; s[j][2 * hf + 1] = p1;
                ps += p0 + p1;
            }
            ps += __shfl_xor_sync(0xffffffffu, ps, 1);
            ps += __shfl_xor_sync(0xffffffffu, ps, 2);
            lrow[hf] = lrow[hf] * fac[hf] + ps;
            mrow[hf] = mn;
        }
#pragma unroll
        for (int j = 0; j < 8; j++) {
            o[j][0] *= fac[0]; o[j][1] *= fac[0];
            o[j][2] *= fac[1]; o[j][3] *= fac[1];
        }

        uint32_t pf[4][4];
#pragma unroll
        for (int kb2 = 0; kb2 < 4; kb2++) {
            pf[kb2][0] = packbf(s[2 * kb2][0],     s[2 * kb2][1]);
            pf[kb2][1] = packbf(s[2 * kb2][2],     s[2 * kb2][3]);
            pf[kb2][2] = packbf(s[2 * kb2 + 1][0], s[2 * kb2 + 1][1]);
            pf[kb2][3] = packbf(s[2 * kb2 + 1][2], s[2 * kb2 + 1][3]);
        }

        uint32_t vbase = kbase + 16384u;
#pragma unroll
        for (int kb2 = 0; kb2 < 4; kb2++) {
            int kb = kb2 * 32 + ((lane >> 4) << 4);
            uint32_t bf[4][4];
#pragma unroll
            for (int j = 0; j < 4; j++)
                ldm_x4(bf[j], vbase + swz((uint32_t)((j * 16 + (lane & 15)) * 128 + kb)));
#pragma unroll
            for (int j2 = 0; j2 < 8; j2++) {
                int jj = j2 >> 1, e = j2 & 1;
                mma16816(o[j2], pf[kb2], bf[jj][e], bf[jj][2 + e]);
            }
        }
        __syncthreads();
    }

    float inv0 = 1.f / lrow[0], inv1 = 1.f / lrow[1];
#pragma unroll
    for (int j2 = 0; j2 < 8; j2++) {
        int col = h * DH_ + j2 * 8 + 2 * (lane & 3);
#pragma unroll
        for (int hf = 0; hf < 2; hf++) {
            int row = t0q + wid * 16 + (lane >> 2) + hf * 8;
            float iv = hf ? inv1 : inv0;
            *(__nv_bfloat162*)&g_aoh[(size_t)row * D_ + col] =
                __floats2bfloat162_rn(o[j2][2 * hf] * iv, o[j2][2 * hf + 1] * iv);
        }
    }
}

// ---------------- auxiliary loss ----------------------------------------------------
__global__ void loss_k(float* out, int do_write) {
    int tid = threadIdx.x;
    float vq = g_mq[tid] * (1.f / NTOK), vk = g_mk[tid] * (1.f / NTOK);
    float s = vq * vq + vk * vk;
#pragma unroll
    for (int off = 16; off; off >>= 1) s += __shfl_xor_sync(0xffffffffu, s, off);
    __shared__ float rs[16];
    if ((tid & 31) == 0) rs[tid >> 5] = s;
    __syncthreads();
    if (tid == 0) {
        float a = 0.f;
        for (int i = 0; i < 16; i++) a += rs[i];
        if (do_write) out[0] = 0.5f * NB_ * (a / H_);
    }
}

// ---------------- launch -----------------------------------------------------------
extern "C" void kernel_launch(void* const* d_in, const int* in_sizes, int n_in,
                              void* d_out, int out_size) {
    const float* inputs = (const float*)d_in[0];
    const float* ln1g   = (const float*)d_in[1];
    const float* ln1b   = (const float*)d_in[2];
    const float* Wq     = (const float*)d_in[3];
    const float* Wk     = (const float*)d_in[4];
    const float* Wv     = (const float*)d_in[5];
    const float* Whq    = (const float*)d_in[6];
    const float* Whk    = (const float*)d_in[7];
    const float* Wo     = (const float*)d_in[8];
    const float* ln2g   = (const float*)d_in[9];
    const float* ln2b   = (const float*)d_in[10];
    const float* W1     = (const float*)d_in[11];
    const float* b1     = (const float*)d_in[12];
    const float* W2     = (const float*)d_in[13];
    const float* b2     = (const float*)d_in[14];
    float* out = (float*)d_out;

    float *qkv, *xres;
    __nv_bfloat16 *xh, *aoh, *yh, *yl, *hh, *hl;
    __nv_bfloat16 *wqkvt, *wot, *w1h, *w1l, *w2h, *w2l;
    cudaGetSymbolAddress((void**)&qkv,  g_qkv);
    cudaGetSymbolAddress((void**)&xres, g_xres);
    cudaGetSymbolAddress((void**)&xh,   g_xh);
    cudaGetSymbolAddress((void**)&aoh,  g_aoh);
    cudaGetSymbolAddress((void**)&yh,   g_yh);
    cudaGetSymbolAddress((void**)&yl,   g_yl);
    cudaGetSymbolAddress((void**)&hh,   g_hh);
    cudaGetSymbolAddress((void**)&hl,   g_hl);
    cudaGetSymbolAddress((void**)&wqkvt, g_WqkvT);
    cudaGetSymbolAddress((void**)&wot,  g_WoT);
    cudaGetSymbolAddress((void**)&w1h,  g_W1Th); cudaGetSymbolAddress((void**)&w1l, g_W1Tl);
    cudaGetSymbolAddress((void**)&w2h,  g_W2Th); cudaGetSymbolAddress((void**)&w2l, g_W2Tl);

    zero_sums_k<<<1, 512>>>();

    dim3 tb(32, 8);
    transpose_bf_k<<<dim3(D_ / 32, D_ / 32), tb>>>(Wq, wqkvt,               nullptr, D_, D_);
    transpose_bf_k<<<dim3(D_ / 32, D_ / 32), tb>>>(Wk, wqkvt + D_ * D_,     nullptr, D_, D_);
    transpose_bf_k<<<dim3(D_ / 32, D_ / 32), tb>>>(Wv, wqkvt + 2 * D_ * D_, nullptr, D_, D_);
    transpose_bf_k<<<dim3(D_ / 32, D_ / 32), tb>>>(Wo, wot, nullptr, D_, D_);
    transpose_bf_k<<<dim3(D_ / 32, MLP_ / 32), tb>>>(W1, w1h, w1l, D_, MLP_);
    transpose_bf_k<<<dim3(MLP_ / 32, D_ / 32), tb>>>(W2, w2h, w2l, MLP_, D_);

    ln_k<<<NTOK, 256>>>(inputs, ln1g, ln1b, xh, nullptr);

    int gpsmem = 1024 + 128 * 132 * 4;           // plain kernel (68.6KB, 2 CTA/SM)
    int g2smem = 1024 + 128 * 132 * 4;           // split kernel (stage covers 64KB tiles)
    cudaFuncSetAttribute(hgemm_p_k, cudaFuncAttributeMaxDynamicSharedMemorySize, gpsmem);
    cudaFuncSetAttribute(hgemm2_k,  cudaFuncAttributeMaxDynamicSharedMemorySize, g2smem);

    // fused QKV: [NTOK, 3072] = xh @ WqkvT^T
    hgemm_p_k<<<dim3(DQKV / GBN, NTOK / GBM), 256, gpsmem>>>(xh, wqkvt, qkv,
                                                             NTOK, DQKV, D_, nullptr);

    build_ext_k<<<NTOK * H_ / 4, 128>>>(Whq, Whk);
    vt_k<<<dim3(B_ * H_, S_ / 32), tb>>>();

    int fasmem = 1024 + 32768 + 2 * 24576;   // ~82 KB
    cudaFuncSetAttribute(fa_k, cudaFuncAttributeMaxDynamicSharedMemorySize, fasmem);
    fa_k<<<B_ * H_ * (S_ / FQM), 256, fasmem>>>();

    // attn @ Wo + residual(inputs) -> xres (fp32)
    hgemm_p_k<<<dim3(D_ / GBN, NTOK / GBM), 256, gpsmem>>>(aoh, wot, xres,
                                                           NTOK, D_, D_, inputs);

    ln_k<<<NTOK, 256>>>(xres, ln2g, ln2b, yh, yl);

    // MLP1: relu(y @ W1 + b1) -> bf16 hi/lo
    hgemm2_k<<<dim3(MLP_ / GBN, NTOK / GBM), 256, g2smem>>>(yh, yl, w1h, w1l,
        nullptr, hh, hl, NTOK, MLP_, D_, b1, nullptr, 1);
    // MLP2: h @ W2 + b2 + xres -> out (fp32); grid 256 <= 296 concurrent -> one wave
    hgemm2_k<<<dim3(D_ / GBN, NTOK / GBM), 256, g2smem>>>(hh, hl, w2h, w2l,
        out, nullptr, nullptr, NTOK, D_, MLP_, b2, xres, 0);

    loss_k<<<1, 512>>>(out + (size_t)NTOK * D_, (out_size > NTOK * D_) ? 1 : 0);
}

// round 16
// speedup vs baseline: 1.0352x; 1.0352x over previous
#include <cuda_runtime.h>
#include <cuda_bf16.h>
#include <math.h>
#include <stdint.h>

// Problem dims
#define B_    2
#define S_    2048
#define D_    1024
#define H_    16
#define DH_   64
#define NB_   32
#define NTOK  4096          // B_*S_
#define MLP_  4096
#define DE_   96            // extended head dim: 64 (content) + 32 (bucket)
#define DQKV  3072          // fused q|k|v row width

// ---------------- scratch (device globals; no allocations allowed) ----------------
__device__ __align__(128) float g_qkv [NTOK * DQKV];   // fused q|k|v (fp32)
__device__ __align__(128) float g_xres[NTOK * D_];
__device__ float g_mq  [H_ * NB_];
__device__ float g_mk  [H_ * NB_];

// bf16 activation buffers
__device__ __align__(128) __nv_bfloat16 g_xh [NTOK * D_];     // ln1 out (plain bf16)
__device__ __align__(128) __nv_bfloat16 g_aoh[NTOK * D_];     // attn out (plain bf16)
__device__ __align__(128) __nv_bfloat16 g_yh [NTOK * D_];     // ln2 out hi
__device__ __align__(128) __nv_bfloat16 g_yl [NTOK * D_];     // ln2 out lo
__device__ __align__(128) __nv_bfloat16 g_hh [NTOK * MLP_];   // mlp hidden hi
__device__ __align__(128) __nv_bfloat16 g_hl [NTOK * MLP_];   // mlp hidden lo
// transposed weights [N,K]: fused QKV + Wo plain bf16; W1/W2 hi/lo split
__device__ __align__(128) __nv_bfloat16 g_WqkvT[DQKV * D_];
__device__ __align__(128) __nv_bfloat16 g_WoT[D_ * D_];
__device__ __align__(128) __nv_bfloat16 g_W1Th[MLP_ * D_], g_W1Tl[MLP_ * D_];
__device__ __align__(128) __nv_bfloat16 g_W2Th[D_ * MLP_], g_W2Tl[D_ * MLP_];

// bf16 FA operands: extended q'/k' [(b*H+h)*S + s][96], V^T [(b*H+h)][dh][S]
__device__ __align__(128) __nv_bfloat16 g_qeb[NTOK * H_ * DE_];
__device__ __align__(128) __nv_bfloat16 g_keb[NTOK * H_ * DE_];
__device__ __align__(128) __nv_bfloat16 g_vt [B_ * H_ * DH_ * S_];

// ================= PTX helpers (baseline PTX only) =================================
__device__ __forceinline__ uint32_t smem_u32(const void* p) {
    uint32_t a;
    asm("{ .reg .u64 t; cvta.to.shared.u64 t, %1; cvt.u32.u64 %0, t; }" : "=r"(a) : "l"(p));
    return a;
}
__device__ __forceinline__ void cp16(uint32_t dst, const void* src) {
    asm volatile("cp.async.cg.shared.global [%0], [%1], 16;" :: "r"(dst), "l"(src));
}
__device__ __forceinline__ void cp_commit() {
    asm volatile("cp.async.commit_group;" ::: "memory");
}
__device__ __forceinline__ void ldm_x4(uint32_t* r, uint32_t a) {
    asm volatile("ldmatrix.sync.aligned.m8n8.x4.shared.b16 {%0,%1,%2,%3}, [%4];"
        : "=r"(r[0]), "=r"(r[1]), "=r"(r[2]), "=r"(r[3]) : "r"(a));
}
__device__ __forceinline__ void mma16816(float* d, const uint32_t* a, uint32_t b0, uint32_t b1) {
    asm volatile("mma.sync.aligned.m16n8k16.row.col.f32.bf16.bf16.f32 "
        "{%0,%1,%2,%3}, {%4,%5,%6,%7}, {%8,%9}, {%0,%1,%2,%3};"
        : "+f"(d[0]), "+f"(d[1]), "+f"(d[2]), "+f"(d[3])
        : "r"(a[0]), "r"(a[1]), "r"(a[2]), "r"(a[3]), "r"(b0), "r"(b1));
}
__device__ __forceinline__ void split_bf(float v, __nv_bfloat16& hi, __nv_bfloat16& lo) {
    hi = __float2bfloat16(v);
    lo = __float2bfloat16(v - __bfloat162float(hi));
}
__device__ __forceinline__ uint32_t packbf(float a, float b) {
    __nv_bfloat162 t = __floats2bfloat162_rn(a, b);
    return *(uint32_t*)&t;
}
__device__ __forceinline__ uint32_t swz(uint32_t off) { return off ^ ((off >> 3) & 0x70u); }

// ---------------- zero the loss accumulators ---------------------------------------
__global__ void zero_sums_k() {
    int i = threadIdx.x;
    if (i < H_ * NB_) { g_mq[i] = 0.f; g_mk[i] = 0.f; }
}

// ---------------- weight transpose + bf16 (optional hi/lo): W[K,N] -> WT[N,K] ------
__global__ void transpose_bf_k(const float* __restrict__ W,
                               __nv_bfloat16* __restrict__ WTh,
                               __nv_bfloat16* __restrict__ WTl, int K, int N) {
    __shared__ float t[32][33];
    int k0 = blockIdx.x * 32, n0 = blockIdx.y * 32;
    int tx = threadIdx.x, ty = threadIdx.y;   // 32 x 8
#pragma unroll
    for (int i = 0; i < 32; i += 8)
        t[ty + i][tx] = W[(size_t)(k0 + ty + i) * N + n0 + tx];
    __syncthreads();
#pragma unroll
    for (int i = 0; i < 32; i += 8) {
        float v = t[tx][ty + i];
        size_t o = (size_t)(n0 + ty + i) * K + k0 + tx;
        if (WTl) {
            __nv_bfloat16 hi, lo; split_bf(v, hi, lo);
            WTh[o] = hi; WTl[o] = lo;
        } else {
            WTh[o] = __float2bfloat16(v);
        }
    }
}

// ---------------- V transpose per head: g_qkv[token][2048+h*64+d] -> g_vt bf16 -----
__global__ void vt_k() {
    __shared__ float t[32][72];
    int bh = blockIdx.x;               // 0..31
    int s0 = blockIdx.y * 32;
    int b = bh >> 4, h = bh & 15;
    int tx = threadIdx.x, ty = threadIdx.y;  // 32 x 8
#pragma unroll
    for (int i = 0; i < 4; i++) {
        int s = ty + i * 8;
        const float* src = g_qkv + (size_t)(b * S_ + s0 + s) * DQKV + 2048 + h * DH_;
        t[s][tx]      = src[tx];
        t[s][tx + 32] = src[tx + 32];
    }
    __syncthreads();
#pragma unroll
    for (int i = 0; i < 8; i++) {
        int d = ty + i * 8;            // 0..63
        g_vt[((size_t)bh * DH_ + d) * S_ + s0 + tx] = __float2bfloat16(t[tx][d]);
    }
}

// ---------------- layernorm: bf16 out (optional lo) --------------------------------
__global__ void ln_k(const float* __restrict__ in, const float* __restrict__ g,
                     const float* __restrict__ b,
                     __nv_bfloat16* __restrict__ oh, __nv_bfloat16* __restrict__ ol) {
    int t = blockIdx.x, tid = threadIdx.x;
    const float* x = in + (size_t)t * D_;
    float v[4]; float s = 0.f, s2 = 0.f;
#pragma unroll
    for (int i = 0; i < 4; i++) { v[i] = x[tid + i * 256]; s += v[i]; s2 += v[i] * v[i]; }
#pragma unroll
    for (int o = 16; o; o >>= 1) {
        s  += __shfl_xor_sync(0xffffffffu, s,  o);
        s2 += __shfl_xor_sync(0xffffffffu, s2, o);
    }
    __shared__ float rs[8], rs2[8];
    __shared__ float mu_s, rstd_s;
    int w = tid >> 5, l = tid & 31;
    if (l == 0) { rs[w] = s; rs2[w] = s2; }
    __syncthreads();
    if (tid == 0) {
        float a = 0.f, a2 = 0.f;
        for (int i = 0; i < 8; i++) { a += rs[i]; a2 += rs2[i]; }
        float mu = a * (1.f / D_);
        float var = a2 * (1.f / D_) - mu * mu;
        mu_s = mu; rstd_s = rsqrtf(var + 1e-6f);
    }
    __syncthreads();
    float mu = mu_s, rstd = rstd_s;
#pragma unroll
    for (int i = 0; i < 4; i++) {
        int c = tid + i * 256;
        float vv = (v[i] - mu) * rstd * g[c] + b[c];
        if (ol) {
            __nv_bfloat16 hi, lo; split_bf(vv, hi, lo);
            oh[(size_t)t * D_ + c] = hi;
            ol[(size_t)t * D_ + c] = lo;
        } else {
            oh[(size_t)t * D_ + c] = __float2bfloat16(vv);
        }
    }
}

#define GBM 128
#define GBN 128
#define GBK 64

// ================= HMMA bf16 plain GEMM (fused QKV / Wo path) ======================
// 128x128 tile, single MMA per term, 32KB/buffer.  (round-14 exact config)
__global__ void __launch_bounds__(256) hgemm_p_k(
    const __nv_bfloat16* __restrict__ Ah, const __nv_bfloat16* __restrict__ Bh,
    float* __restrict__ Cf, int M, int N, int K,
    const float* __restrict__ res)
{
    extern __shared__ char smem[];
    uint32_t sb = smem_u32(smem);
    uint32_t s0 = (sb + 1023u) & ~1023u;
    int tid = threadIdx.x, wid = tid >> 5, lane = tid & 31;
    int bn = blockIdx.x * GBN, bm = blockIdx.y * GBM;
    int wm = (wid & 3) * 32;
    int wn = (wid >> 2) * 64;

    auto prefetch = [&](int buf, int k0) {
        uint32_t base = s0 + (uint32_t)buf * 32768u;
#pragma unroll
        for (int i = 0; i < 4; i++) {
            int idx = tid + i * 256;
            int row = idx >> 3; int ch = (idx & 7) * 16;
            uint32_t sw = swz((uint32_t)(row * 128 + ch));
            cp16(base + sw,          (const char*)Ah + ((size_t)(bm + row) * K + k0) * 2 + ch);
            cp16(base + 16384u + sw, (const char*)Bh + ((size_t)(bn + row) * K + k0) * 2 + ch);
        }
        cp_commit();
    };

    prefetch(0, 0);
    prefetch(1, GBK);

    float acc[2][8][4];
#pragma unroll
    for (int i = 0; i < 2; i++)
#pragma unroll
        for (int j = 0; j < 8; j++)
#pragma unroll
            for (int c = 0; c < 4; c++) acc[i][j][c] = 0.f;

    int NK = K / GBK;
    for (int kt = 0; kt < NK; kt++) {
        int cur = kt & 1;
        if (kt == NK - 1) asm volatile("cp.async.wait_group 0;" ::: "memory");
        else              asm volatile("cp.async.wait_group 1;" ::: "memory");
        __syncthreads();

        uint32_t base = s0 + (uint32_t)cur * 32768u;
#pragma unroll
        for (int ks = 0; ks < 4; ks++) {
            int kb = ks * 32 + ((lane >> 4) << 4);
            uint32_t ah[2][4];
#pragma unroll
            for (int i = 0; i < 2; i++) {
                uint32_t sw = swz((uint32_t)((wm + i * 16 + (lane & 15)) * 128 + kb));
                ldm_x4(ah[i], base + sw);
            }
            uint32_t bh[4][4];
#pragma unroll
            for (int j = 0; j < 4; j++) {
                uint32_t sw = swz((uint32_t)((wn + j * 16 + (lane & 15)) * 128 + kb));
                ldm_x4(bh[j], base + 16384u + sw);
            }
#pragma unroll
            for (int i = 0; i < 2; i++)
#pragma unroll
                for (int j2 = 0; j2 < 8; j2++) {
                    int jj = j2 >> 1, e = j2 & 1;
                    mma16816(acc[i][j2], ah[i], bh[jj][e], bh[jj][2 + e]);
                }
        }
        __syncthreads();
        if (kt + 2 < NK) prefetch(cur, (kt + 2) * GBK);
    }

    float* stg = (float*)(smem + (s0 - sb));
#pragma unroll
    for (int i = 0; i < 2; i++)
#pragma unroll
        for (int j2 = 0; j2 < 8; j2++) {
            int r0 = wm + i * 16 + (lane >> 2);
            int c0 = wn + j2 * 8 + 2 * (lane & 3);
            stg[r0 * 132 + c0]           = acc[i][j2][0];
            stg[r0 * 132 + c0 + 1]       = acc[i][j2][1];
            stg[(r0 + 8) * 132 + c0]     = acc[i][j2][2];
            stg[(r0 + 8) * 132 + c0 + 1] = acc[i][j2][3];
        }
    __syncthreads();
#pragma unroll
    for (int i = 0; i < 64; i++) {
        int idx = tid + i * 256;
        int rr = idx >> 7, cc = idx & 127;
        int gr = bm + rr, gc = bn + cc;
        float v = stg[rr * 132 + cc];
        if (res) v += res[(size_t)gr * N + gc];
        Cf[(size_t)gr * N + gc] = v;
    }
}

// ================= HMMA bf16 split-3 GEMM, 128x64 tile, BK=64, 2 CTAs/SM ===========
// C = Ah·Bh + Al·Bh + Ah·Bl.  Round-14 config, but the three terms are emitted as
// THREE PASSES over all (i,j2) fragments per k16-step: accumulator reuse distance
// grows 1 -> 16 instructions (16 independent HMMA chains), hiding the accumulator
// RAW latency. Per-accumulator FP order is unchanged -> bit-identical result.
__global__ void __launch_bounds__(256, 2) hgemm2_k(
    const __nv_bfloat16* __restrict__ Ah, const __nv_bfloat16* __restrict__ Al,
    const __nv_bfloat16* __restrict__ Bh, const __nv_bfloat16* __restrict__ Bl,
    float* __restrict__ Cf,
    __nv_bfloat16* __restrict__ Cbh, __nv_bfloat16* __restrict__ Cbl,
    int M, int N, int K,
    const float* __restrict__ bias, const float* __restrict__ res, int relu)
{
    extern __shared__ char smem[];
    uint32_t sb = smem_u32(smem);
    uint32_t s0 = (sb + 1023u) & ~1023u;
    int tid = threadIdx.x, wid = tid >> 5, lane = tid & 31;
    int bn = blockIdx.x * 64, bm = blockIdx.y * 128;
    int wm = (wid & 3) * 32;                 // warp M offset (4 warps over 128)
    int wn = (wid >> 2) * 32;                // warp N offset (2 warps over 64)

    auto prefetch = [&](int buf, int k0) {
        uint32_t base = s0 + (uint32_t)buf * 49152u;
#pragma unroll
        for (int i = 0; i < 4; i++) {        // A hi+lo: 128 rows x 8 chunks
            int idx = tid + i * 256;
            int row = idx >> 3; int ch = (idx & 7) * 16;
            uint32_t sw = swz((uint32_t)(row * 128 + ch));
            size_t ga = ((size_t)(bm + row) * K + k0) * 2 + ch;
            cp16(base + sw,          (const char*)Ah + ga);
            cp16(base + 16384u + sw, (const char*)Al + ga);
        }
#pragma unroll
        for (int i = 0; i < 2; i++) {        // B hi+lo: 64 rows x 8 chunks
            int idx = tid + i * 256;
            int row = idx >> 3; int ch = (idx & 7) * 16;
            uint32_t sw = swz((uint32_t)(row * 128 + ch));
            size_t gb = ((size_t)(bn + row) * K + k0) * 2 + ch;
            cp16(base + 32768u + sw, (const char*)Bh + gb);
            cp16(base + 40960u + sw, (const char*)Bl + gb);
        }
        cp_commit();
    };

    prefetch(0, 0);
    prefetch(1, GBK);

    float acc[2][4][4];
#pragma unroll
    for (int i = 0; i < 2; i++)
#pragma unroll
        for (int j = 0; j < 4; j++)
#pragma unroll
            for (int c = 0; c < 4; c++) acc[i][j][c] = 0.f;

    int NK = K / GBK;
    for (int kt = 0; kt < NK; kt++) {
        int cur = kt & 1;
        if (kt == NK - 1) asm volatile("cp.async.wait_group 0;" ::: "memory");
        else              asm volatile("cp.async.wait_group 1;" ::: "memory");
        __syncthreads();

        uint32_t base = s0 + (uint32_t)cur * 49152u;
#pragma unroll
        for (int ks = 0; ks < 4; ks++) {
            int kb = ks * 32 + ((lane >> 4) << 4);
            uint32_t ah[2][4], al2[2][4];
#pragma unroll
            for (int i = 0; i < 2; i++) {
                uint32_t sw = swz((uint32_t)((wm + i * 16 + (lane & 15)) * 128 + kb));
                ldm_x4(ah[i],  base + sw);
                ldm_x4(al2[i], base + 16384u + sw);
            }
            uint32_t bh2[2][4], bl2[2][4];
#pragma unroll
            for (int j = 0; j < 2; j++) {
                uint32_t sw = swz((uint32_t)((wn + j * 16 + (lane & 15)) * 128 + kb));
                ldm_x4(bh2[j], base + 32768u + sw);
                ldm_x4(bl2[j], base + 40960u + sw);
            }
            // pass 1: Ah*Bh for all 8 fragments
#pragma unroll
            for (int i = 0; i < 2; i++)
#pragma unroll
                for (int j2 = 0; j2 < 4; j2++) {
                    int jj = j2 >> 1, e = j2 & 1;
                    mma16816(acc[i][j2], ah[i], bh2[jj][e], bh2[jj][2 + e]);
                }
            // pass 2: Al*Bh
#pragma unroll
            for (int i = 0; i < 2; i++)
#pragma unroll
                for (int j2 = 0; j2 < 4; j2++) {
                    int jj = j2 >> 1, e = j2 & 1;
                    mma16816(acc[i][j2], al2[i], bh2[jj][e], bh2[jj][2 + e]);
                }
            // pass 3: Ah*Bl
#pragma unroll
            for (int i = 0; i < 2; i++)
#pragma unroll
                for (int j2 = 0; j2 < 4; j2++) {
                    int jj = j2 >> 1, e = j2 & 1;
                    mma16816(acc[i][j2], ah[i], bl2[jj][e], bl2[jj][2 + e]);
                }
        }
        __syncthreads();
        if (kt + 2 < NK) prefetch(cur, (kt + 2) * GBK);
    }

    // epilogue: stage fp32 through smem (aliases tiles; 128 x 68 floats = 34.8KB)
    float* stg = (float*)(smem + (s0 - sb));
#pragma unroll
    for (int i = 0; i < 2; i++)
#pragma unroll
        for (int j2 = 0; j2 < 4; j2++) {
            int r0 = wm + i * 16 + (lane >> 2);
            int c0 = wn + j2 * 8 + 2 * (lane & 3);
            stg[r0 * 68 + c0]           = acc[i][j2][0];
            stg[r0 * 68 + c0 + 1]       = acc[i][j2][1];
            stg[(r0 + 8) * 68 + c0]     = acc[i][j2][2];
            stg[(r0 + 8) * 68 + c0 + 1] = acc[i][j2][3];
        }
    __syncthreads();

    if (Cbh) {
#pragma unroll
        for (int i = 0; i < 16; i++) {       // 128 x 32 bf162 pairs
            int idx = tid + i * 256;
            int rr = idx >> 5, cp = idx & 31;
            int gr = bm + rr, gc = bn + 2 * cp;
            float v0 = stg[rr * 68 + 2 * cp];
            float v1 = stg[rr * 68 + 2 * cp + 1];
            if (bias) { v0 += bias[gc]; v1 += bias[gc + 1]; }
            if (res)  { v0 += res[(size_t)gr * N + gc]; v1 += res[(size_t)gr * N + gc + 1]; }
            if (relu) { v0 = fmaxf(v0, 0.f); v1 = fmaxf(v1, 0.f); }
            __nv_bfloat16 h0, l0, h1, l1;
            split_bf(v0, h0, l0); split_bf(v1, h1, l1);
            __nv_bfloat162 hh2; hh2.x = h0; hh2.y = h1;
            __nv_bfloat162 ll2; ll2.x = l0; ll2.y = l1;
            *(__nv_bfloat162*)&Cbh[(size_t)gr * N + gc] = hh2;
            *(__nv_bfloat162*)&Cbl[(size_t)gr * N + gc] = ll2;
        }
    } else {
#pragma unroll
        for (int i = 0; i < 32; i++) {       // 128 x 64 floats
            int idx = tid + i * 256;
            int rr = idx >> 6, cc = idx & 63;
            int gr = bm + rr, gc = bn + cc;
            float v = stg[rr * 68 + cc];
            if (bias) v += bias[gc];
            if (res)  v += res[(size_t)gr * N + gc];
            if (relu) v = fmaxf(v, 0.f);
            Cf[(size_t)gr * N + gc] = v;
        }
    }
}

// ---------------- bucket softmax + extended q'/k' build (bf16) + loss --------------
__global__ void build_ext_k(const float* __restrict__ Whq, const float* __restrict__ Whk) {
    int wg   = blockIdx.x * 4 + (threadIdx.x >> 5);
    int lane = threadIdx.x & 31;
    int t = wg >> 4, h = wg & 15;
    int b = t >> 11, s = t & 2047;
    const float* q = g_qkv + (size_t)t * DQKV + h * DH_;
    const float* k = g_qkv + (size_t)t * DQKV + 1024 + h * DH_;
    float ql = 0.f, kl = 0.f;
#pragma unroll 8
    for (int f = 0; f < DH_; f++) {
        float qv = q[f], kv = k[f];
        ql += qv * Whq[(h * DH_ + f) * NB_ + lane];
        kl += kv * Whk[(h * DH_ + f) * NB_ + lane];
    }
    float mq = ql, mk = kl;
#pragma unroll
    for (int o = 16; o; o >>= 1) {
        mq = fmaxf(mq, __shfl_xor_sync(0xffffffffu, mq, o));
        mk = fmaxf(mk, __shfl_xor_sync(0xffffffffu, mk, o));
    }
    float eq = __expf(ql - mq), ek = __expf(kl - mk);
    float sq = eq, sk = ek;
#pragma unroll
    for (int o = 16; o; o >>= 1) {
        sq += __shfl_xor_sync(0xffffffffu, sq, o);
        sk += __shfl_xor_sync(0xffffffffu, sk, o);
    }
    float qb = eq / sq, kb = ek / sk;
    size_t base = ((size_t)(b * H_ + h) * S_ + s) * DE_;
    __nv_bfloat16* qe = g_qeb + base;
    __nv_bfloat16* ke = g_keb + base;
    qe[64 + lane] = __float2bfloat16(0.1f * qb);   // cluster weight folded into q'
    ke[64 + lane] = __float2bfloat16(kb);
    qe[lane]      = __float2bfloat16(0.125f * q[lane]);
    qe[lane + 32] = __float2bfloat16(0.125f * q[lane + 32]);
    ke[lane]      = __float2bfloat16(k[lane]);
    ke[lane + 32] = __float2bfloat16(k[lane + 32]);
    atomicAdd(&g_mq[h * NB_ + lane], qb);
    atomicAdd(&g_mk[h * NB_ + lane], kb);
}

// ================= HMMA flash attention ============================================
#define FQM 128
__global__ void __launch_bounds__(256) fa_k() {
    extern __shared__ char smem[];
    uint32_t sb = smem_u32(smem);
    uint32_t s0 = (sb + 1023u) & ~1023u;
    uint32_t Q0 = s0, Q1 = s0 + 16384u;            // Q content / bucket subtiles
    uint32_t KV = s0 + 32768u;                     // 2 x 24KB: K0,K1,Vt per buffer
    int tid = threadIdx.x, wid = tid >> 5, lane = tid & 31;
    int blk = blockIdx.x;
    int qt = blk & 15, h = (blk >> 4) & 15, b = blk >> 8;
    int bh = b * H_ + h;
    int t0q = b * S_ + qt * FQM;

    const char* qsrc = (const char*)(g_qeb + ((size_t)bh * S_ + qt * FQM) * DE_);
    const char* ksrc0 = (const char*)(g_keb + (size_t)bh * S_ * DE_);
    const char* vsrc0 = (const char*)(g_vt + (size_t)bh * DH_ * S_);

#pragma unroll
    for (int i = 0; i < 6; i++) {
        int idx = tid + i * 256;
        int row = idx / 12, c = idx - row * 12;
        uint32_t dst = (c < 8) ? (Q0 + swz((uint32_t)(row * 128 + c * 16)))
                               : (Q1 + swz((uint32_t)(row * 128 + (c - 8) * 16)));
        cp16(dst, qsrc + (size_t)row * (DE_ * 2) + c * 16);
    }
    cp_commit();

    auto prefetch = [&](int buf, int kt) {
        uint32_t base = KV + (uint32_t)buf * 24576u;
        const char* ks = ksrc0 + (size_t)(kt * 64) * (DE_ * 2);
#pragma unroll
        for (int i = 0; i < 3; i++) {
            int idx = tid + i * 256;
            int row = idx / 12, c = idx - row * 12;
            uint32_t dst = (c < 8) ? (base + swz((uint32_t)(row * 128 + c * 16)))
                                   : (base + 8192u + swz((uint32_t)(row * 128 + (c - 8) * 16)));
            cp16(dst, ks + (size_t)row * (DE_ * 2) + c * 16);
        }
#pragma unroll
        for (int i = 0; i < 2; i++) {
            int idx = tid + i * 256;
            int row = idx >> 3, c = idx & 7;
            cp16(base + 16384u + swz((uint32_t)(row * 128 + c * 16)),
                 vsrc0 + (size_t)row * (S_ * 2) + kt * 128 + c * 16);
        }
        cp_commit();
    };

    prefetch(0, 0);
    asm volatile("cp.async.wait_group 1;" ::: "memory");
    __syncthreads();

    uint32_t qf[6][4];
#pragma unroll
    for (int ks = 0; ks < 6; ks++) {
        uint32_t base = (ks < 4) ? Q0 : Q1;
        int kb = ((ks < 4) ? ks * 32 : (ks - 4) * 32) + ((lane >> 4) << 4);
        ldm_x4(qf[ks], base + swz((uint32_t)((wid * 16 + (lane & 15)) * 128 + kb)));
    }

    float o[8][4];
#pragma unroll
    for (int j = 0; j < 8; j++)
#pragma unroll
        for (int c = 0; c < 4; c++) o[j][c] = 0.f;
    float mrow[2] = {-1e30f, -1e30f}, lrow[2] = {0.f, 0.f};

    const int NT = S_ / 64;
    for (int kt = 0; kt < NT; kt++) {
        int cur = kt & 1;
        if (kt + 1 < NT) { prefetch(cur ^ 1, kt + 1); asm volatile("cp.async.wait_group 1;" ::: "memory"); }
        else             { asm volatile("cp.async.wait_group 0;" ::: "memory"); }
        __syncthreads();

        uint32_t kbase = KV + (uint32_t)cur * 24576u;

        float s[8][4];
#pragma unroll
        for (int j = 0; j < 8; j++)
#pragma unroll
            for (int c = 0; c < 4; c++) s[j][c] = 0.f;
#pragma unroll
        for (int ks = 0; ks < 6; ks++) {
            uint32_t base = (ks < 4) ? kbase : (kbase + 8192u);
            int kb = ((ks < 4) ? ks * 32 : (ks - 4) * 32) + ((lane >> 4) << 4);
            uint32_t bf[4][4];
#pragma unroll
            for (int j = 0; j < 4; j++)
                ldm_x4(bf[j], base + swz((uint32_t)((j * 16 + (lane & 15)) * 128 + kb)));
#pragma unroll
            for (int j2 = 0; j2 < 8; j2++) {
                int jj = j2 >> 1, e = j2 & 1;
                mma16816(s[j2], qf[ks], bf[jj][e], bf[jj][2 + e]);
            }
        }

        float fac[2];
#pragma unroll
        for (int hf = 0; hf < 2; hf++) {
            float mt = -1e30f;
#pragma unroll
            for (int j = 0; j < 8; j++)
                mt = fmaxf(mt, fmaxf(s[j][2 * hf], s[j][2 * hf + 1]));
            mt = fmaxf(mt, __shfl_xor_sync(0xffffffffu, mt, 1));
            mt = fmaxf(mt, __shfl_xor_sync(0xffffffffu, mt, 2));
            float mn = fmaxf(mrow[hf], mt);
            fac[hf] = __expf(mrow[hf] - mn);
            float ps = 0.f;
#pragma unroll
            for (int j = 0; j < 8; j++) {
                float p0 = __expf(s[j][2 * hf]     - mn);
                float p1 = __expf(s[j][2 * hf + 1] - mn);
                s[j][2 * hf] = p0; s[j][2 * hf + 1] = p1;
                ps += p0 + p1;
            }
            ps += __shfl_xor_sync(0xffffffffu, ps, 1);
            ps += __shfl_xor_sync(0xffffffffu, ps, 2);
            lrow[hf] = lrow[hf] * fac[hf] + ps;
            mrow[hf] = mn;
        }
#pragma unroll
        for (int j = 0; j < 8; j++) {
            o[j][0] *= fac[0]; o[j][1] *= fac[0];
            o[j][2] *= fac[1]; o[j][3] *= fac[1];
        }

        uint32_t pf[4][4];
#pragma unroll
        for (int kb2 = 0; kb2 < 4; kb2++) {
            pf[kb2][0] = packbf(s[2 * kb2][0],     s[2 * kb2][1]);
            pf[kb2][1] = packbf(s[2 * kb2][2],     s[2 * kb2][3]);
            pf[kb2][2] = packbf(s[2 * kb2 + 1][0], s[2 * kb2 + 1][1]);
            pf[kb2][3] = packbf(s[2 * kb2 + 1][2], s[2 * kb2 + 1][3]);
        }

        uint32_t vbase = kbase + 16384u;
#pragma unroll
        for (int kb2 = 0; kb2 < 4; kb2++) {
            int kb = kb2 * 32 + ((lane >> 4) << 4);
            uint32_t bf[4][4];
#pragma unroll
            for (int j = 0; j < 4; j++)
                ldm_x4(bf[j], vbase + swz((uint32_t)((j * 16 + (lane & 15)) * 128 + kb)));
#pragma unroll
            for (int j2 = 0; j2 < 8; j2++) {
                int jj = j2 >> 1, e = j2 & 1;
                mma16816(o[j2], pf[kb2], bf[jj][e], bf[jj][2 + e]);
            }
        }
        __syncthreads();
    }

    float inv0 = 1.f / lrow[0], inv1 = 1.f / lrow[1];
#pragma unroll
    for (int j2 = 0; j2 < 8; j2++) {
        int col = h * DH_ + j2 * 8 + 2 * (lane & 3);
#pragma unroll
        for (int hf = 0; hf < 2; hf++) {
            int row = t0q + wid * 16 + (lane >> 2) + hf * 8;
            float iv = hf ? inv1 : inv0;
            *(__nv_bfloat162*)&g_aoh[(size_t)row * D_ + col] =
                __floats2bfloat162_rn(o[j2][2 * hf] * iv, o[j2][2 * hf + 1] * iv);
        }
    }
}

// ---------------- auxiliary loss ----------------------------------------------------
__global__ void loss_k(float* out, int do_write) {
    int tid = threadIdx.x;
    float vq = g_mq[tid] * (1.f / NTOK), vk = g_mk[tid] * (1.f / NTOK);
    float s = vq * vq + vk * vk;
#pragma unroll
    for (int off = 16; off; off >>= 1) s += __shfl_xor_sync(0xffffffffu, s, off);
    __shared__ float rs[16];
    if ((tid & 31) == 0) rs[tid >> 5] = s;
    __syncthreads();
    if (tid == 0) {
        float a = 0.f;
        for (int i = 0; i < 16; i++) a += rs[i];
        if (do_write) out[0] = 0.5f * NB_ * (a / H_);
    }
}

// ---------------- launch -----------------------------------------------------------
extern "C" void kernel_launch(void* const* d_in, const int* in_sizes, int n_in,
                              void* d_out, int out_size) {
    const float* inputs = (const float*)d_in[0];
    const float* ln1g   = (const float*)d_in[1];
    const float* ln1b   = (const float*)d_in[2];
    const float* Wq     = (const float*)d_in[3];
    const float* Wk     = (const float*)d_in[4];
    const float* Wv     = (const float*)d_in[5];
    const float* Whq    = (const float*)d_in[6];
    const float* Whk    = (const float*)d_in[7];
    const float* Wo     = (const float*)d_in[8];
    const float* ln2g   = (const float*)d_in[9];
    const float* ln2b   = (const float*)d_in[10];
    const float* W1     = (const float*)d_in[11];
    const float* b1     = (const float*)d_in[12];
    const float* W2     = (const float*)d_in[13];
    const float* b2     = (const float*)d_in[14];
    float* out = (float*)d_out;

    float *qkv, *xres;
    __nv_bfloat16 *xh, *aoh, *yh, *yl, *hh, *hl;
    __nv_bfloat16 *wqkvt, *wot, *w1h, *w1l, *w2h, *w2l;
    cudaGetSymbolAddress((void**)&qkv,  g_qkv);
    cudaGetSymbolAddress((void**)&xres, g_xres);
    cudaGetSymbolAddress((void**)&xh,   g_xh);
    cudaGetSymbolAddress((void**)&aoh,  g_aoh);
    cudaGetSymbolAddress((void**)&yh,   g_yh);
    cudaGetSymbolAddress((void**)&yl,   g_yl);
    cudaGetSymbolAddress((void**)&hh,   g_hh);
    cudaGetSymbolAddress((void**)&hl,   g_hl);
    cudaGetSymbolAddress((void**)&wqkvt, g_WqkvT);
    cudaGetSymbolAddress((void**)&wot,  g_WoT);
    cudaGetSymbolAddress((void**)&w1h,  g_W1Th); cudaGetSymbolAddress((void**)&w1l, g_W1Tl);
    cudaGetSymbolAddress((void**)&w2h,  g_W2Th); cudaGetSymbolAddress((void**)&w2l, g_W2Tl);

    zero_sums_k<<<1, 512>>>();

    dim3 tb(32, 8);
    transpose_bf_k<<<dim3(D_ / 32, D_ / 32), tb>>>(Wq, wqkvt,               nullptr, D_, D_);
    transpose_bf_k<<<dim3(D_ / 32, D_ / 32), tb>>>(Wk, wqkvt + D_ * D_,     nullptr, D_, D_);
    transpose_bf_k<<<dim3(D_ / 32, D_ / 32), tb>>>(Wv, wqkvt + 2 * D_ * D_, nullptr, D_, D_);
    transpose_bf_k<<<dim3(D_ / 32, D_ / 32), tb>>>(Wo, wot, nullptr, D_, D_);
    transpose_bf_k<<<dim3(D_ / 32, MLP_ / 32), tb>>>(W1, w1h, w1l, D_, MLP_);
    transpose_bf_k<<<dim3(MLP_ / 32, D_ / 32), tb>>>(W2, w2h, w2l, MLP_, D_);

    ln_k<<<NTOK, 256>>>(inputs, ln1g, ln1b, xh, nullptr);

    int gpsmem = 1024 + 128 * 132 * 4;           // plain kernel
    int g2smem = 1024 + 2 * 49152;               // split-3 128x64 kernel (2 CTA/SM)
    cudaFuncSetAttribute(hgemm_p_k, cudaFuncAttributeMaxDynamicSharedMemorySize, gpsmem);
    cudaFuncSetAttribute(hgemm2_k,  cudaFuncAttributeMaxDynamicSharedMemorySize, g2smem);

    // fused QKV: [NTOK, 3072] = xh @ WqkvT^T
    hgemm_p_k<<<dim3(DQKV / GBN, NTOK / GBM), 256, gpsmem>>>(xh, wqkvt, qkv,
                                                             NTOK, DQKV, D_, nullptr);

    build_ext_k<<<NTOK * H_ / 4, 128>>>(Whq, Whk);
    vt_k<<<dim3(B_ * H_, S_ / 32), tb>>>();

    int fasmem = 1024 + 32768 + 2 * 24576;   // ~82 KB
    cudaFuncSetAttribute(fa_k, cudaFuncAttributeMaxDynamicSharedMemorySize, fasmem);
    fa_k<<<B_ * H_ * (S_ / FQM), 256, fasmem>>>();

    // attn @ Wo + residual(inputs) -> xres (fp32)
    hgemm_p_k<<<dim3(D_ / GBN, NTOK / GBM), 256, gpsmem>>>(aoh, wot, xres,
                                                           NTOK, D_, D_, inputs);

    ln_k<<<NTOK, 256>>>(xres, ln2g, ln2b, yh, yl);

    // MLP1: relu(y @ W1 + b1) -> bf16 hi/lo
    hgemm2_k<<<dim3(MLP_ / 64, NTOK / 128), 256, g2smem>>>(yh, yl, w1h, w1l,
        nullptr, hh, hl, NTOK, MLP_, D_, b1, nullptr, 1);
    // MLP2: h @ W2 + b2 + xres -> out (fp32)
    hgemm2_k<<<dim3(D_ / 64, NTOK / 128), 256, g2smem>>>(hh, hl, w2h, w2l,
        out, nullptr, nullptr, NTOK, D_, MLP_, b2, xres, 0);

    loss_k<<<1, 512>>>(out + (size_t)NTOK * D_, (out_size > NTOK * D_) ? 1 : 0);
}